// round 5
// baseline (speedup 1.0000x reference)
#include <cuda_runtime.h>
#include <math.h>

#define IMG_H 512
#define IMG_W 512
#define NB    8
#define NC    3
#define HID   64
#define NPIX  (IMG_H*IMG_W)
#define KTOP  26214
#define OUT_XOUT (NB*NC*NPIX)
#define PLANE NPIX
#define BSTRIDE (NC*NPIX)

#define TW 32
#define TH 16
#define HS_W 34
#define HS_H 18
#define NPOS (HS_W*HS_H)   /* 612 */

/* blob layout (floats) */
#define OFF_W1 0          /* [27][64]            1728 */
#define OFF_W2 1728       /* [64][9][4]          2304 */
#define OFF_B1 4032       /* 64 */
#define OFF_B2 4096       /* 4  */
#define OFF_CW 4100       /* 12 */
#define OFF_CB 4112       /* 4  */
#define BLOB_FLOATS 4116
/* smem layout */
#define SM_COL 4116       /* 4 */
#define SM_X   4120       /* 3*20*36 = 2160 */
#define SM_H   6280       /* 64*612 = 39168 */
#define SMEM_FLOATS 45448
#define SMEM_BYTES (SMEM_FLOATS*4)

__device__ float    g_blob[BLOB_FLOATS];
__device__ float    g_pmean[24*8];
__device__ float    g_color[24];
__device__ float    g_m[NB*NPIX];
__device__ float    g_bright[NB*NPIX];
__device__ unsigned g_hist[4][NB][256];
__device__ unsigned g_prefix[NB];
__device__ unsigned g_remk[NB];
__device__ float    g_gt[NB][64][3];
__device__ unsigned g_eqcB[NB][64];
__device__ unsigned g_eqstart[NB][64];
__device__ float    g_eqsB[NB][64][3];

__device__ __forceinline__ float2 ffma2(float2 a, float2 b, float2 c) {
    float2 d;
    asm("{\n\t"
        ".reg .b64 ra, rb, rc, rd;\n\t"
        "mov.b64 ra, {%2,%3};\n\t"
        "mov.b64 rb, {%4,%5};\n\t"
        "mov.b64 rc, {%6,%7};\n\t"
        "fma.rn.f32x2 rd, ra, rb, rc;\n\t"
        "mov.b64 {%0,%1}, rd;\n\t"
        "}"
        : "=f"(d.x), "=f"(d.y)
        : "f"(a.x), "f"(a.y), "f"(b.x), "f"(b.y), "f"(c.x), "f"(c.y));
    return d;
}

__device__ __forceinline__ float sigm(float v) { return 1.f / (1.f + expf(-v)); }

/* ---------------- prep ---------------- */
__global__ void prep_kernel(const float* __restrict__ w1, const float* __restrict__ b1,
                            const float* __restrict__ w2, const float* __restrict__ b2,
                            const float* __restrict__ cw, const float* __restrict__ cb) {
    int tid = threadIdx.x;
    for (int i = tid; i < 1728; i += 256) {           /* w1: [oc][27] -> [tap][oc] */
        int t = i >> 6, oc = i & 63;
        g_blob[OFF_W1 + t*64 + oc] = w1[oc*27 + t];
    }
    for (int i = tid; i < 2304; i += 256) {           /* w2: [oc][ic][9] -> [ic][tap][4] */
        int ic = i / 36, r = i % 36, t = r >> 2, oc = r & 3;
        g_blob[OFF_W2 + i] = (oc < 3) ? w2[oc*576 + ic*9 + t] : 0.f;
    }
    for (int i = tid; i < 64; i += 256) g_blob[OFF_B1 + i] = b1[i];
    if (tid < 4)  g_blob[OFF_B2 + tid] = (tid < 3) ? b2[tid] : 0.f;
    if (tid < 12) g_blob[OFF_CW + tid] = cw[tid];
    if (tid < 4)  g_blob[OFF_CB + tid] = cb[tid];
    unsigned* hz = &g_hist[0][0][0];
    for (int i = tid; i < 4*NB*256; i += 256) hz[i] = 0u;
    if (tid < NB) { g_prefix[tid] = 0u; g_remk[tid] = KTOP; }
}

/* ---------------- mean / color ---------------- */
__device__ float block_reduce256(float v, float* sbuf) {
    int tid = threadIdx.x;
    sbuf[tid] = v; __syncthreads();
    for (int s = 128; s > 0; s >>= 1) {
        if (tid < s) sbuf[tid] += sbuf[tid + s];
        __syncthreads();
    }
    float r = sbuf[0]; __syncthreads();
    return r;
}

__global__ void meanA_kernel(const float* __restrict__ x) {
    __shared__ float sbuf[256];
    int chunk = blockIdx.x, bc = blockIdx.y, tid = threadIdx.x;
    int base = bc * NPIX + chunk * 32768;
    float s = 0.f;
    for (int i = tid; i < 32768; i += 256) s += x[base + i];
    float r = block_reduce256(s, sbuf);
    if (tid == 0) g_pmean[bc*8 + chunk] = r;
}

__global__ void meanB_kernel(const float* __restrict__ color_w, const float* __restrict__ color_b) {
    __shared__ float mm[24];
    int tid = threadIdx.x;
    if (tid < 24) {
        float s = 0.f;
        for (int j = 0; j < 8; j++) s += g_pmean[tid*8 + j];
        mm[tid] = s * (1.f / (float)NPIX);
    }
    __syncthreads();
    if (tid < 24) {
        int b = tid / 3, c = tid % 3;
        float lin = color_b[c];
        for (int j = 0; j < 3; j++) lin += mm[b*3 + j] * color_w[c*3 + j];
        g_color[tid] = sigm(lin);
    }
}

/* ---------------- main fused kernel ---------------- */
__global__ void __launch_bounds__(512, 1)
main_kernel(const float* __restrict__ x, float* __restrict__ out) {
    extern __shared__ float sm[];
    int tid = threadIdx.x;
    int b  = blockIdx.z;
    int r0 = blockIdx.y * TH;
    int c0 = blockIdx.x * TW;

    for (int i = tid; i < BLOB_FLOATS; i += 512) sm[i] = g_blob[i];
    if (tid < 3) sm[SM_COL + tid] = g_color[b*3 + tid];

    /* x tile: 3 x 20 x 36, origin (r0-2, c0-2), zero outside image */
    for (int i = tid; i < 3*20*36; i += 512) {
        int ci = i / 720;
        int rr = (i % 720) / 36;
        int cc = i % 36;
        int gr = r0 - 2 + rr, gc = c0 - 2 + cc;
        float v = 0.f;
        if ((unsigned)gr < 512u && (unsigned)gc < 512u)
            v = x[b*BSTRIDE + ci*PLANE + gr*512 + gc];
        sm[SM_X + i] = v;
    }
    __syncthreads();

    /* conv1: h on 18x34 region, 64 channels */
    for (int pos = tid; pos < NPOS; pos += 512) {
        int pr = pos / HS_W, pc = pos % HS_W;
        int gr = r0 - 1 + pr, gc = c0 - 1 + pc;
        float* hdst = &sm[SM_H + pos];
        if ((unsigned)gr >= 512u || (unsigned)gc >= 512u) {
            for (int oc = 0; oc < HID; oc++) hdst[oc*NPOS] = 0.f;
        } else {
            float2 acc[32];
            #pragma unroll
            for (int k = 0; k < 32; k++) acc[k] = *(const float2*)&sm[OFF_B1 + 2*k];
            #pragma unroll
            for (int ci = 0; ci < 3; ci++) {
                #pragma unroll
                for (int dr = 0; dr < 3; dr++) {
                    #pragma unroll
                    for (int dc = 0; dc < 3; dc++) {
                        float xv = sm[SM_X + ci*720 + (pr+dr)*36 + (pc+dc)];
                        const float2* wp = (const float2*)&sm[OFF_W1 + (ci*9 + dr*3 + dc)*64];
                        float2 xv2 = make_float2(xv, xv);
                        #pragma unroll
                        for (int k = 0; k < 32; k++) acc[k] = ffma2(xv2, wp[k], acc[k]);
                    }
                }
            }
            #pragma unroll
            for (int k = 0; k < 32; k++) {
                hdst[(2*k)*NPOS]   = fmaxf(acc[k].x, 0.f);
                hdst[(2*k+1)*NPOS] = fmaxf(acc[k].y, 0.f);
            }
        }
    }
    __syncthreads();

    /* conv2 + sigmoid + color + 1x1 + x_out */
    int py = tid >> 5, px = tid & 31;
    float2 a01 = make_float2(sm[OFF_B2], sm[OFF_B2+1]);
    float  a2  = sm[OFF_B2+2];
    const float* hbase = &sm[SM_H + py*HS_W + px];
    for (int ic = 0; ic < HID; ic++) {
        const float* hcc = hbase + ic*NPOS;
        const float* wp  = &sm[OFF_W2 + ic*36];
        #pragma unroll
        for (int t = 0; t < 9; t++) {
            float hv = hcc[(t/3)*HS_W + (t%3)];
            float2 w01 = *(const float2*)&wp[t*4];
            float  w2v = wp[t*4 + 2];
            a01 = ffma2(make_float2(hv, hv), w01, a01);
            a2  = fmaf(hv, w2v, a2);
        }
    }
    float ih0 = sigm(a01.x) * sm[SM_COL + 0];
    float ih1 = sigm(a01.y) * sm[SM_COL + 1];
    float ih2 = sigm(a2)    * sm[SM_COL + 2];
    const float* cw = &sm[OFF_CW];
    const float* cb = &sm[OFF_CB];
    float K = cb[0] + cw[0]*ih0 + cw[1]*ih1 + cw[2]*ih2;
    int pix = (r0 + py)*512 + (c0 + px);
    float mx = -1e30f;
    #pragma unroll
    for (int c = 0; c < 3; c++) {
        float Bt = cb[1+c] + cw[(1+c)*3+0]*ih0 + cw[(1+c)*3+1]*ih1 + cw[(1+c)*3+2]*ih2;
        float xv = sm[SM_X + c*720 + (py+2)*36 + (px+2)];
        float xo = K*xv - Bt + xv;
        out[b*BSTRIDE + c*PLANE + pix] = xo;
        mx = fmaxf(mx, xo);
    }
    g_m[b*NPIX + pix] = mx;
}

/* ---------------- bright (reflect pad, 3x3) ---------------- */
__global__ void bright_kernel() {
    int b = blockIdx.y;
    int p = blockIdx.x*256 + threadIdx.x;
    int r = p >> 9, c = p & 511;
    const float* m = &g_m[b*NPIX];
    float acc = 0.f;
    #pragma unroll
    for (int dr = 0; dr < 3; dr++) {
        int rr = r + dr - 1; rr = rr < 0 ? 1 : (rr > 511 ? 510 : rr);
        #pragma unroll
        for (int dc = 0; dc < 3; dc++) {
            int cc = c + dc - 1; cc = cc < 0 ? 1 : (cc > 511 ? 510 : cc);
            float w = (dr == 1 && dc == 1) ? 1.0f : (1.f/9.f);
            acc += w * m[rr*512 + cc];
        }
    }
    g_bright[b*NPIX + p] = fmaxf(acc, 0.f);
}

/* ---------------- radix select ---------------- */
__global__ void hist_kernel(int pass) {
    __shared__ unsigned h[256];
    int b = blockIdx.y, tid = threadIdx.x;
    h[tid] = 0; __syncthreads();
    unsigned pref = g_prefix[b];
    int shift = 24 - 8*pass;
    int base = b*NPIX + blockIdx.x*1024;
    for (int i = tid; i < 1024; i += 256) {
        unsigned u = __float_as_uint(g_bright[base + i]);
        bool ok = (pass == 0) || ((u >> (shift + 8)) == pref);
        if (ok) atomicAdd(&h[(u >> shift) & 255], 1u);
    }
    __syncthreads();
    if (h[tid]) atomicAdd(&g_hist[pass][b][tid], h[tid]);
}

__global__ void scan_kernel(int pass) {
    int b = blockIdx.x;
    if (threadIdx.x == 0) {
        unsigned remk = g_remk[b], cum = 0, pref = g_prefix[b], sel = 0;
        for (int bin = 255; bin >= 0; bin--) {
            unsigned c = g_hist[pass][b][bin];
            if (cum + c >= remk) { sel = (unsigned)bin; break; }
            cum += c;
        }
        g_prefix[b] = (pref << 8) | sel;
        g_remk[b] = remk - cum;
    }
}

__global__ void sel1_kernel(const float* __restrict__ outp) {
    __shared__ float s0[256], s1[256], s2[256];
    __shared__ unsigned sc[256];
    int b = blockIdx.y, blk = blockIdx.x, tid = threadIdx.x;
    unsigned T = g_prefix[b];
    const float* br  = &g_bright[b*NPIX];
    const float* img = outp + b*BSTRIDE;
    int base = blk*4096;
    float a0 = 0, a1 = 0, a2 = 0; unsigned ec = 0;
    for (int i = tid; i < 4096; i += 256) {
        int p = base + i;
        unsigned u = __float_as_uint(br[p]);
        if (u > T) { a0 += img[p*3]; a1 += img[p*3+1]; a2 += img[p*3+2]; }
        else if (u == T) ec++;
    }
    s0[tid]=a0; s1[tid]=a1; s2[tid]=a2; sc[tid]=ec; __syncthreads();
    for (int s = 128; s > 0; s >>= 1) {
        if (tid < s) { s0[tid]+=s0[tid+s]; s1[tid]+=s1[tid+s]; s2[tid]+=s2[tid+s]; sc[tid]+=sc[tid+s]; }
        __syncthreads();
    }
    if (tid == 0) {
        g_gt[b][blk][0]=s0[0]; g_gt[b][blk][1]=s1[0]; g_gt[b][blk][2]=s2[0];
        g_eqcB[b][blk]=sc[0];
    }
}

__global__ void sel2_kernel() {
    int b = blockIdx.x;
    if (threadIdx.x == 0) {
        unsigned run = 0;
        for (int i = 0; i < 64; i++) { g_eqstart[b][i] = run; run += g_eqcB[b][i]; }
    }
}

__global__ void sel3_kernel(const float* __restrict__ outp) {
    __shared__ unsigned scnt[256];
    __shared__ float s0[256], s1[256], s2[256];
    int b = blockIdx.y, blk = blockIdx.x, tid = threadIdx.x;
    unsigned T = g_prefix[b], remk = g_remk[b];
    const float* br  = &g_bright[b*NPIX];
    const float* img = outp + b*BSTRIDE;
    int start = blk*4096 + tid*16;
    unsigned cnt = 0;
    for (int j = 0; j < 16; j++) if (__float_as_uint(br[start+j]) == T) cnt++;
    scnt[tid] = cnt; __syncthreads();
    if (tid == 0) {
        unsigned run = 0;
        for (int i = 0; i < 256; i++) { unsigned c = scnt[i]; scnt[i] = run; run += c; }
    }
    __syncthreads();
    unsigned rank = g_eqstart[b][blk] + scnt[tid];
    float a0 = 0, a1 = 0, a2 = 0;
    for (int j = 0; j < 16; j++) {
        int p = start + j;
        if (__float_as_uint(br[p]) == T) {
            if (rank < remk) { a0 += img[p*3]; a1 += img[p*3+1]; a2 += img[p*3+2]; }
            rank++;
        }
    }
    s0[tid]=a0; s1[tid]=a1; s2[tid]=a2; __syncthreads();
    for (int s = 128; s > 0; s >>= 1) {
        if (tid < s) { s0[tid]+=s0[tid+s]; s1[tid]+=s1[tid+s]; s2[tid]+=s2[tid+s]; }
        __syncthreads();
    }
    if (tid == 0) { g_eqsB[b][blk][0]=s0[0]; g_eqsB[b][blk][1]=s1[0]; g_eqsB[b][blk][2]=s2[0]; }
}

__global__ void sel4_kernel(float* __restrict__ outp) {
    int tid = threadIdx.x;
    if (tid < 24) {
        int b = tid / 3, c = tid % 3;
        float s = 0.f;
        for (int i = 0; i < 64; i++) s += g_gt[b][i][c] + g_eqsB[b][i][c];
        outp[OUT_XOUT + tid] = s * (1.f / (float)KTOP);
    }
}

/* ---------------- launch ---------------- */
extern "C" void kernel_launch(void* const* d_in, const int* in_sizes, int n_in,
                              void* d_out, int out_size) {
    const float* x   = (const float*)d_in[0];
    const float* w1  = (const float*)d_in[1];
    const float* b1  = (const float*)d_in[2];
    const float* w2  = (const float*)d_in[3];
    const float* b2  = (const float*)d_in[4];
    const float* cwm = (const float*)d_in[5];   /* color_w (3x3) */
    const float* cbm = (const float*)d_in[6];   /* color_b (3)   */
    const float* cw  = (const float*)d_in[7];   /* conv_w (4x3)  */
    const float* cb  = (const float*)d_in[8];   /* conv_b (4)    */
    float* out = (float*)d_out;

    cudaFuncSetAttribute(main_kernel, cudaFuncAttributeMaxDynamicSharedMemorySize, SMEM_BYTES);

    /* FIX (R3): prep must receive conv_w/conv_b, not color_w/color_b */
    prep_kernel<<<1, 256>>>(w1, b1, w2, b2, cw, cb);
    meanA_kernel<<<dim3(8, 24), 256>>>(x);
    meanB_kernel<<<1, 32>>>(cwm, cbm);
    main_kernel<<<dim3(IMG_W/TW, IMG_H/TH, NB), 512, SMEM_BYTES>>>(x, out);
    bright_kernel<<<dim3(NPIX/256, NB), 256>>>();
    for (int p = 0; p < 4; p++) {
        hist_kernel<<<dim3(256, NB), 256>>>(p);
        scan_kernel<<<NB, 32>>>(p);
    }
    sel1_kernel<<<dim3(64, NB), 256>>>(out);
    sel2_kernel<<<NB, 32>>>();
    sel3_kernel<<<dim3(64, NB), 256>>>(out);
    sel4_kernel<<<1, 32>>>(out);
}